// round 10
// baseline (speedup 1.0000x reference)
#include <cuda_runtime.h>

// 2x nearest-neighbor upsample:
// in:  float32 [16, 64, 256, 256]  (1024 planes of 256x256)
// out: float32 [16, 64, 512, 512]
//
// R9 structure + 256-bit stores (sm_100+ st.global.v8.f32):
//   idx -> (plane, h, o8); input float4 index == idx (same linear index).
//   v=(x,y,z,w) -> 8 outputs (x,x,y,y,z,z,w,w), one STG.256 per output row
//   (rows 2h and 2h+1). Per warp: 1 x LDG.128 (512B) + 2 x STG.256 (1024B),
//   all lane-contiguous, 32B-aligned per lane.
// Measured context: pinned at HBM mixed-stream ceiling (~6.7 TB/s, DRAM 84%).

#define W_OUT8 64                   // 8-float groups per output row (512/8)

__global__ void __launch_bounds__(512) upsample2x_v8_kernel(
    const float4* __restrict__ in4, float* __restrict__ out, int total)
{
    int idx = blockIdx.x * blockDim.x + threadIdx.x;
    if (idx >= total) return;

    // idx -> (plane, h, o8); input float4 index == idx
    int o8    = idx & (W_OUT8 - 1);         // 0..63
    int h     = (idx >> 6) & 255;           // 0..255
    int plane = idx >> 14;                  // 0..1023

    float4 v = in4[idx];

    // output address (floats) for row 2h, column 8*o8
    long long base = ((long long)plane * 512 + 2 * h) * 512 + o8 * 8;
    float* p0 = out + base;                 // row 2h
    float* p1 = p0 + 512;                   // row 2h+1

    asm volatile(
        "st.global.v8.f32 [%0], {%2, %2, %3, %3, %4, %4, %5, %5};\n\t"
        "st.global.v8.f32 [%1], {%2, %2, %3, %3, %4, %4, %5, %5};"
        :: "l"(p0), "l"(p1),
           "f"(v.x), "f"(v.y), "f"(v.z), "f"(v.w)
        : "memory");
}

extern "C" void kernel_launch(void* const* d_in, const int* in_sizes, int n_in,
                              void* d_out, int out_size)
{
    const float4* in4 = (const float4*)d_in[0];
    float* out = (float*)d_out;

    int total = in_sizes[0] / 4;            // 16,777,216 threads
    int threads = 512;
    int blocks = (total + threads - 1) / threads;

    upsample2x_v8_kernel<<<blocks, threads>>>(in4, out, total);
}